// round 1
// baseline (speedup 1.0000x reference)
#include <cuda_runtime.h>
#include <cstdint>

// Segment-sum: out[src[e], f] += edge_w[e, f], F=16.
// One thread per (edge, quad-of-4-floats). Vectorized L2 reduction via
// red.global.add.v4.f32 (sm_90+): 1 atomic op per 16 bytes instead of 4.

static constexpr int F = 16;

__global__ void zero_out_kernel(float4* __restrict__ out, int n_vec) {
    int i = blockIdx.x * blockDim.x + threadIdx.x;
    if (i < n_vec) out[i] = make_float4(0.f, 0.f, 0.f, 0.f);
}

__global__ void scatter_add_kernel(const int* __restrict__ src,
                                   const float4* __restrict__ w4,
                                   float* __restrict__ out,
                                   int E) {
    int tid = blockIdx.x * blockDim.x + threadIdx.x;
    int total = E * 4;               // 4 quads per edge (F=16)
    if (tid >= total) return;
    int e = tid >> 2;
    int q = tid & 3;
    int s = src[e];                  // edge[0][e]
    float4 w = w4[tid];              // edge_w[e, q*4 .. q*4+3], coalesced
    float* dst = out + (size_t)s * F + q * 4;   // 16B aligned
    asm volatile("red.global.add.v4.f32 [%0], {%1, %2, %3, %4};"
                 :: "l"(dst), "f"(w.x), "f"(w.y), "f"(w.z), "f"(w.w)
                 : "memory");
}

extern "C" void kernel_launch(void* const* d_in, const int* in_sizes, int n_in,
                              void* d_out, int out_size) {
    const int* edge  = (const int*)d_in[0];        // [2, E] row-major; row 0 = src
    const float4* w4 = (const float4*)d_in[1];     // [E, 16] f32 == [E*4] float4
    float* out       = (float*)d_out;              // [N, 16] f32

    const int E = in_sizes[1] / F;                 // 3,200,000
    const int n_out_vec = out_size / 4;            // N*16/4 float4s

    // 1) zero the poisoned output
    {
        int threads = 256;
        int blocks = (n_out_vec + threads - 1) / threads;
        zero_out_kernel<<<blocks, threads>>>((float4*)d_out, n_out_vec);
    }
    // 2) vectorized scatter-add
    {
        int total = E * 4;
        int threads = 256;
        int blocks = (total + threads - 1) / threads;
        scatter_add_kernel<<<blocks, threads>>>(edge, w4, out, E);
    }
}

// round 2
// speedup vs baseline: 1.0090x; 1.0090x over previous
#include <cuda_runtime.h>
#include <cstdint>

// Segment-sum: out[src[e], f] += edge_w[e, f], F=16.
// Item = (edge, quad-of-4-floats). 4 items per thread, grid-strided so
// adjacent threads read adjacent float4s (perfect coalescing). All loads
// issued before any reduction => per-thread MLP of 8 outstanding loads.
// red.global.add.v4.f32: one 16B L2 reduction per item.

static constexpr int F = 16;

__global__ void zero_out_kernel(float4* __restrict__ out, int n_vec) {
    int i = blockIdx.x * blockDim.x + threadIdx.x;
    if (i < n_vec) out[i] = make_float4(0.f, 0.f, 0.f, 0.f);
}

__device__ __forceinline__ void red_v4(float* dst, float4 w) {
    asm volatile("red.global.add.v4.f32 [%0], {%1, %2, %3, %4};"
                 :: "l"(dst), "f"(w.x), "f"(w.y), "f"(w.z), "f"(w.w)
                 : "memory");
}

__global__ void __launch_bounds__(256) scatter_add_kernel(
        const int* __restrict__ src,
        const float4* __restrict__ w4,
        float* __restrict__ out,
        int total) {
    const int G = blockDim.x * gridDim.x;
    const int t = blockIdx.x * blockDim.x + threadIdx.x;

    const int i0 = t;
    const int i1 = t + G;
    const int i2 = t + 2 * G;
    const int i3 = t + 3 * G;

    // --- issue all index loads (4B, warp-coalesced, 4x broadcast per edge) ---
    int s0 = 0, s1 = 0, s2 = 0, s3 = 0;
    if (i0 < total) s0 = __ldg(&src[i0 >> 2]);
    if (i1 < total) s1 = __ldg(&src[i1 >> 2]);
    if (i2 < total) s2 = __ldg(&src[i2 >> 2]);
    if (i3 < total) s3 = __ldg(&src[i3 >> 2]);

    // --- issue all payload loads (16B, streaming / evict-first) ---
    float4 w0, w1, w2, w3;
    if (i0 < total) w0 = __ldcs(&w4[i0]);
    if (i1 < total) w1 = __ldcs(&w4[i1]);
    if (i2 < total) w2 = __ldcs(&w4[i2]);
    if (i3 < total) w3 = __ldcs(&w4[i3]);

    // --- reductions last ---
    if (i0 < total) red_v4(out + (size_t)s0 * F + (i0 & 3) * 4, w0);
    if (i1 < total) red_v4(out + (size_t)s1 * F + (i1 & 3) * 4, w1);
    if (i2 < total) red_v4(out + (size_t)s2 * F + (i2 & 3) * 4, w2);
    if (i3 < total) red_v4(out + (size_t)s3 * F + (i3 & 3) * 4, w3);
}

extern "C" void kernel_launch(void* const* d_in, const int* in_sizes, int n_in,
                              void* d_out, int out_size) {
    const int* edge  = (const int*)d_in[0];        // [2, E] row-major; row 0 = src
    const float4* w4 = (const float4*)d_in[1];     // [E, 16] f32 == [E*4] float4
    float* out       = (float*)d_out;              // [N, 16] f32

    const int E = in_sizes[1] / F;                 // 3,200,000
    const int n_out_vec = out_size / 4;            // N*16/4 float4s

    // 1) zero the poisoned output
    {
        int threads = 256;
        int blocks = (n_out_vec + threads - 1) / threads;
        zero_out_kernel<<<blocks, threads>>>((float4*)d_out, n_out_vec);
    }
    // 2) vectorized scatter-add, 4 items/thread
    {
        int total = E * 4;                          // 12.8M items
        int threads = 256;
        int items_per_block = threads * 4;
        int blocks = (total + items_per_block - 1) / items_per_block;  // 12500
        scatter_add_kernel<<<blocks, threads>>>(edge, w4, out, total);
    }
}